// round 1
// baseline (speedup 1.0000x reference)
#include <cuda_runtime.h>
#include <math_constants.h>

#define DM   1024
#define HS   64
#define BB   4
#define TT   2048
#define ROWS (BB * TT)   /* 8192 */
#define NS   4           /* key splits */
#define SPLIT 512
#define KTILE 16

/* ---------------- device scratch (no allocation allowed) ---------------- */
__device__ float g_q[ROWS * HS];
__device__ float g_k[ROWS * HS];
__device__ float g_v[ROWS * HS];
__device__ float g_po[NS * ROWS * HS];
__device__ float g_pm[NS * ROWS];
__device__ float g_pl[NS * ROWS];

/* ---------------- fused QKV projection: [8192,1024] x [1024,64] x3 ------ */
__global__ __launch_bounds__(256)
void qkv_kernel(const float* __restrict__ x,
                const float* __restrict__ Wq, const float* __restrict__ bq,
                const float* __restrict__ Wk, const float* __restrict__ bk,
                const float* __restrict__ Wv) {
    __shared__ float As[32][65];   /* transposed A tile, pad -> conflict-free */
    __shared__ float Bs[32][64];

    const int which = blockIdx.y;                 /* 0=q 1=k 2=v */
    const float* __restrict__ W = (which == 0) ? Wq : ((which == 1) ? Wk : Wv);
    float* __restrict__ out = (which == 0) ? g_q : ((which == 1) ? g_k : g_v);

    const int row0 = blockIdx.x * 64;
    const int tid  = threadIdx.x;
    const int tx   = tid & 15;    /* col group */
    const int ty   = tid >> 4;    /* row group */

    float acc[4][4] = {};

    for (int k0 = 0; k0 < DM; k0 += 32) {
        #pragma unroll
        for (int i = 0; i < 2; i++) {
            int idx = tid + i * 256;
            /* A: 64 rows x 32 cols, stored transposed */
            int r = idx >> 3;
            int c = (idx & 7) << 2;
            float4 a = *(const float4*)(x + (size_t)(row0 + r) * DM + k0 + c);
            As[c + 0][r] = a.x; As[c + 1][r] = a.y;
            As[c + 2][r] = a.z; As[c + 3][r] = a.w;
            /* B: 32 rows x 64 cols */
            int rb = idx >> 4;
            int cb = (idx & 15) << 2;
            *(float4*)&Bs[rb][cb] = *(const float4*)(W + (size_t)(k0 + rb) * HS + cb);
        }
        __syncthreads();
        #pragma unroll
        for (int k = 0; k < 32; k++) {
            float a0 = As[k][ty * 4 + 0];
            float a1 = As[k][ty * 4 + 1];
            float a2 = As[k][ty * 4 + 2];
            float a3 = As[k][ty * 4 + 3];
            float4 bv = *(const float4*)&Bs[k][tx * 4];
            acc[0][0] = fmaf(a0, bv.x, acc[0][0]); acc[0][1] = fmaf(a0, bv.y, acc[0][1]);
            acc[0][2] = fmaf(a0, bv.z, acc[0][2]); acc[0][3] = fmaf(a0, bv.w, acc[0][3]);
            acc[1][0] = fmaf(a1, bv.x, acc[1][0]); acc[1][1] = fmaf(a1, bv.y, acc[1][1]);
            acc[1][2] = fmaf(a1, bv.z, acc[1][2]); acc[1][3] = fmaf(a1, bv.w, acc[1][3]);
            acc[2][0] = fmaf(a2, bv.x, acc[2][0]); acc[2][1] = fmaf(a2, bv.y, acc[2][1]);
            acc[2][2] = fmaf(a2, bv.z, acc[2][2]); acc[2][3] = fmaf(a2, bv.w, acc[2][3]);
            acc[3][0] = fmaf(a3, bv.x, acc[3][0]); acc[3][1] = fmaf(a3, bv.y, acc[3][1]);
            acc[3][2] = fmaf(a3, bv.z, acc[3][2]); acc[3][3] = fmaf(a3, bv.w, acc[3][3]);
        }
        __syncthreads();
    }

    float4 bias = make_float4(0.f, 0.f, 0.f, 0.f);
    if (which == 0)      bias = *(const float4*)&bq[tx * 4];
    else if (which == 1) bias = *(const float4*)&bk[tx * 4];

    #pragma unroll
    for (int i = 0; i < 4; i++) {
        float4 v;
        v.x = acc[i][0] + bias.x;
        v.y = acc[i][1] + bias.y;
        v.z = acc[i][2] + bias.z;
        v.w = acc[i][3] + bias.w;
        *(float4*)&out[(size_t)(row0 + ty * 4 + i) * HS + tx * 4] = v;
    }
}

/* ---------------- causal flash-attention, split over keys --------------- */
__global__ __launch_bounds__(128)
void attn_split_kernel() {
    const int ks  = blockIdx.x;          /* key split 0..NS-1 */
    const int qt  = blockIdx.y;          /* query tile 0..15 (128 rows each) */
    const int b   = blockIdx.z;          /* batch 0..3 */
    const int tid = threadIdx.x;

    const int r    = qt * 128 + tid;     /* query row within batch */
    const int grow = b * TT + r;         /* global row */
    const int k_lo = ks * SPLIT;
    const int k_hi = min(k_lo + SPLIT, qt * 128 + 128);  /* causal clip */

    if (k_lo >= k_hi) {                  /* uniform across block */
        g_pm[ks * ROWS + grow] = -CUDART_INF_F;
        g_pl[ks * ROWS + grow] = 0.f;
        return;
    }

    __shared__ float4 Ks[KTILE * 16];
    __shared__ float4 Vs[KTILE * 16];

    float4 qv[16];
    {
        const float4* qp = (const float4*)(g_q + (size_t)grow * HS);
        #pragma unroll
        for (int i = 0; i < 16; i++) qv[i] = qp[i];
    }

    float4 o[16];
    #pragma unroll
    for (int i = 0; i < 16; i++) o[i] = make_float4(0.f, 0.f, 0.f, 0.f);
    float m = -CUDART_INF_F;
    float l = 0.f;

    for (int j0 = k_lo; j0 < k_hi; j0 += KTILE) {
        __syncthreads();
        {
            const float4* kp = (const float4*)(g_k + (size_t)(b * TT + j0) * HS);
            const float4* vp = (const float4*)(g_v + (size_t)(b * TT + j0) * HS);
            #pragma unroll
            for (int i = 0; i < (KTILE * 16) / 128; i++) {
                Ks[tid + i * 128] = kp[tid + i * 128];
                Vs[tid + i * 128] = vp[tid + i * 128];
            }
        }
        __syncthreads();

        float sc[KTILE];
        float tmax = -CUDART_INF_F;
        #pragma unroll
        for (int j = 0; j < KTILE; j++) {
            float4 a = make_float4(0.f, 0.f, 0.f, 0.f);
            #pragma unroll
            for (int d = 0; d < 16; d++) {
                float4 kv = Ks[j * 16 + d];
                a.x = fmaf(qv[d].x, kv.x, a.x);
                a.y = fmaf(qv[d].y, kv.y, a.y);
                a.z = fmaf(qv[d].z, kv.z, a.z);
                a.w = fmaf(qv[d].w, kv.w, a.w);
            }
            float s = ((a.x + a.y) + (a.z + a.w)) * 8.0f;  /* *sqrt(hs) per ref */
            sc[j] = (j0 + j <= r) ? s : -CUDART_INF_F;
            tmax = fmaxf(tmax, sc[j]);
        }

        float mnew = fmaxf(m, tmax);
        if (mnew != -CUDART_INF_F) {          /* tile had >=1 valid key */
            float scale = __expf(m - mnew);   /* m==-inf -> 0, safe */
            m = mnew;
            l *= scale;
            #pragma unroll
            for (int d = 0; d < 16; d++) {
                o[d].x *= scale; o[d].y *= scale;
                o[d].z *= scale; o[d].w *= scale;
            }
            #pragma unroll
            for (int j = 0; j < KTILE; j++) {
                float p = __expf(sc[j] - mnew);   /* masked -> 0 */
                l += p;
                #pragma unroll
                for (int d = 0; d < 16; d++) {
                    float4 vv = Vs[j * 16 + d];
                    o[d].x = fmaf(p, vv.x, o[d].x);
                    o[d].y = fmaf(p, vv.y, o[d].y);
                    o[d].z = fmaf(p, vv.z, o[d].z);
                    o[d].w = fmaf(p, vv.w, o[d].w);
                }
            }
        }
    }

    g_pm[ks * ROWS + grow] = m;
    g_pl[ks * ROWS + grow] = l;
    float4* po = (float4*)(g_po + ((size_t)ks * ROWS + grow) * HS);
    #pragma unroll
    for (int i = 0; i < 16; i++) po[i] = o[i];
}

/* ---------------- combine split partials -------------------------------- */
__global__ __launch_bounds__(256)
void attn_combine_kernel(float* __restrict__ out) {
    int t = blockIdx.x * blockDim.x + threadIdx.x;   /* (row, d4) */
    if (t >= ROWS * 16) return;
    int row = t >> 4;
    int d4  = t & 15;

    float mm[NS], ll[NS];
    float m = -CUDART_INF_F;
    #pragma unroll
    for (int s = 0; s < NS; s++) {
        mm[s] = g_pm[s * ROWS + row];
        ll[s] = g_pl[s * ROWS + row];
        m = fmaxf(m, mm[s]);
    }

    float l = 0.f;
    float4 acc = make_float4(0.f, 0.f, 0.f, 0.f);
    #pragma unroll
    for (int s = 0; s < NS; s++) {
        if (ll[s] > 0.f) {
            float w = __expf(mm[s] - m);
            l += ll[s] * w;
            float4 p = ((const float4*)g_po)[((size_t)s * ROWS + row) * 16 + d4];
            acc.x = fmaf(w, p.x, acc.x);
            acc.y = fmaf(w, p.y, acc.y);
            acc.z = fmaf(w, p.z, acc.z);
            acc.w = fmaf(w, p.w, acc.w);
        }
    }
    float inv = 1.f / l;
    float4 res = make_float4(acc.x * inv, acc.y * inv, acc.z * inv, acc.w * inv);
    ((float4*)out)[(size_t)row * 16 + d4] = res;
}

/* ---------------- launch ------------------------------------------------ */
extern "C" void kernel_launch(void* const* d_in, const int* in_sizes, int n_in,
                              void* d_out, int out_size) {
    (void)in_sizes; (void)n_in; (void)out_size;
    const float* x  = (const float*)d_in[0];
    const float* Wq = (const float*)d_in[1];
    const float* bq = (const float*)d_in[2];
    const float* Wk = (const float*)d_in[3];
    const float* bk = (const float*)d_in[4];
    const float* Wv = (const float*)d_in[5];
    /* d_in[6] = mask flag; setup always passes 1 (causal) */

    qkv_kernel<<<dim3(ROWS / 64, 3), 256>>>(x, Wq, bq, Wk, bk, Wv);
    attn_split_kernel<<<dim3(NS, TT / 128, BB), 128>>>();
    attn_combine_kernel<<<(ROWS * 16 + 255) / 256, 256>>>((float*)d_out);
}

// round 2
// speedup vs baseline: 1.0726x; 1.0726x over previous
#include <cuda_runtime.h>
#include <math_constants.h>

#define DM   1024
#define HS   64
#define BB   4
#define TT   2048
#define ROWS (BB * TT)        /* 8192 */
#define NS   16               /* key splits (SPLIT = q-tile = 128) */
#define SPLIT 128
#define KTILE 16
#define TRI  136              /* 16*17/2 active (qt,ks) pairs per batch */

typedef unsigned long long u64;

/* ---------------- f32x2 packed math helpers ---------------------------- */
__device__ __forceinline__ void fma2(u64& d, u64 a, u64 b) {
    asm("fma.rn.f32x2 %0, %1, %2, %3;" : "=l"(d) : "l"(a), "l"(b), "l"(d));
}
__device__ __forceinline__ void mul2(u64& d, u64 a, u64 b) {
    asm("mul.rn.f32x2 %0, %1, %2;" : "=l"(d) : "l"(a), "l"(b));
}
__device__ __forceinline__ void add2(u64& d, u64 a, u64 b) {
    asm("add.rn.f32x2 %0, %1, %2;" : "=l"(d) : "l"(a), "l"(b));
}
__device__ __forceinline__ u64 dup2(float x) {
    u64 r;
    unsigned u = __float_as_uint(x);
    asm("mov.b64 %0, {%1, %1};" : "=l"(r) : "r"(u));
    return r;
}
__device__ __forceinline__ float2 unpk(u64 v) {
    unsigned lo, hi;
    asm("mov.b64 {%0, %1}, %2;" : "=r"(lo), "=r"(hi) : "l"(v));
    return make_float2(__uint_as_float(lo), __uint_as_float(hi));
}

/* ---------------- device scratch ---------------------------------------- */
__device__ float g_q[ROWS * HS];
__device__ float g_k[ROWS * HS];
__device__ float g_v[ROWS * HS];
__device__ float g_po[(size_t)NS * ROWS * HS];
__device__ float g_pm[NS * ROWS];
__device__ float g_pl[NS * ROWS];

/* ---------------- fused QKV projection (f32x2) --------------------------
 * 64x64 tile per block, 128 threads, 8 rows x 4 cols (=2 pairs) per thread,
 * BK = 32, prefetched global loads. */
__global__ __launch_bounds__(128)
void qkv_kernel(const float* __restrict__ x,
                const float* __restrict__ Wq, const float* __restrict__ bq,
                const float* __restrict__ Wk, const float* __restrict__ bk,
                const float* __restrict__ Wv) {
    __shared__ float As[32][68];   /* transposed A: [k][row], stride 68 (16B-mult, conflict-free) */
    __shared__ float Bs[32][64];   /* [k][col] */

    const int which = blockIdx.y;
    const float* __restrict__ W = (which == 0) ? Wq : ((which == 1) ? Wk : Wv);
    float* __restrict__ out = (which == 0) ? g_q : ((which == 1) ? g_k : g_v);

    const int row0 = blockIdx.x * 64;
    const int tid  = threadIdx.x;
    const int tx   = tid & 15;      /* col group: 4 cols  */
    const int ty   = tid >> 4;      /* row group: 8 rows  */

    /* loader assignment */
    const int arow = tid & 63;
    const int ac4  = (tid >> 6) * 4;   /* 4 float4s along k per thread */
    const int brow = tid & 31;
    const int bc4  = (tid >> 5) * 4;   /* 4 float4s along cols per thread */

    const float* xA = x + (size_t)(row0 + arow) * DM + ac4 * 4;
    const float* wB = W + (size_t)brow * HS + bc4 * 4;

    float4 pa[4], pb[4];
    #pragma unroll
    for (int i = 0; i < 4; i++) {
        pa[i] = *(const float4*)(xA + i * 4);
        pb[i] = *(const float4*)(wB + i * 4);
    }

    u64 acc[8][2];
    #pragma unroll
    for (int i = 0; i < 8; i++) { acc[i][0] = 0ull; acc[i][1] = 0ull; }

    for (int k0 = 0; k0 < DM; k0 += 32) {
        /* store staged tile */
        #pragma unroll
        for (int i = 0; i < 4; i++) {
            int c = (ac4 + i) * 4;
            As[c + 0][arow] = pa[i].x;
            As[c + 1][arow] = pa[i].y;
            As[c + 2][arow] = pa[i].z;
            As[c + 3][arow] = pa[i].w;
            *(float4*)&Bs[brow][(bc4 + i) * 4] = pb[i];
        }
        __syncthreads();

        if (k0 + 32 < DM) {     /* prefetch next tile */
            xA += 32;
            wB += (size_t)32 * HS;
            #pragma unroll
            for (int i = 0; i < 4; i++) {
                pa[i] = *(const float4*)(xA + i * 4);
                pb[i] = *(const float4*)(wB + i * 4);
            }
        }

        #pragma unroll
        for (int k = 0; k < 32; k++) {
            ulonglong2 bb = *(const ulonglong2*)&Bs[k][tx * 4];
            float4 a0 = *(const float4*)&As[k][ty * 8];
            float4 a1 = *(const float4*)&As[k][ty * 8 + 4];
            u64 ad[8];
            ad[0] = dup2(a0.x); ad[1] = dup2(a0.y);
            ad[2] = dup2(a0.z); ad[3] = dup2(a0.w);
            ad[4] = dup2(a1.x); ad[5] = dup2(a1.y);
            ad[6] = dup2(a1.z); ad[7] = dup2(a1.w);
            #pragma unroll
            for (int rr = 0; rr < 8; rr++) {
                fma2(acc[rr][0], ad[rr], bb.x);
                fma2(acc[rr][1], ad[rr], bb.y);
            }
        }
        __syncthreads();
    }

    float4 bias = make_float4(0.f, 0.f, 0.f, 0.f);
    if (which == 0)      bias = *(const float4*)&bq[tx * 4];
    else if (which == 1) bias = *(const float4*)&bk[tx * 4];

    #pragma unroll
    for (int rr = 0; rr < 8; rr++) {
        float2 p0 = unpk(acc[rr][0]);
        float2 p1 = unpk(acc[rr][1]);
        float4 v;
        v.x = p0.x + bias.x; v.y = p0.y + bias.y;
        v.z = p1.x + bias.z; v.w = p1.y + bias.w;
        *(float4*)&out[(size_t)(row0 + ty * 8 + rr) * HS + tx * 4] = v;
    }
}

/* ---------------- causal flash-attention (f32x2, triangle grid) --------- */
__global__ __launch_bounds__(128)
void attn_split_kernel() {
    /* decode triangle index -> (qt, ks), ks <= qt, all blocks do 128 keys */
    int t = blockIdx.x;
    int b = blockIdx.y;
    int qt = (int)((sqrtf(8.f * (float)t + 1.f) - 1.f) * 0.5f);
    while ((qt + 1) * (qt + 2) / 2 <= t) qt++;
    while (qt * (qt + 1) / 2 > t) qt--;
    int ks = t - qt * (qt + 1) / 2;

    const int tid  = threadIdx.x;
    const int r    = qt * SPLIT + tid;       /* query row within batch */
    const int grow = b * TT + r;

    __shared__ float4 Ks[KTILE * 16];
    __shared__ float4 Vs[KTILE * 16];

    u64 q2[32];
    {
        const ulonglong2* qp = (const ulonglong2*)(g_q + (size_t)grow * HS);
        #pragma unroll
        for (int i = 0; i < 16; i++) {
            ulonglong2 v = qp[i];
            q2[2 * i] = v.x; q2[2 * i + 1] = v.y;
        }
    }

    u64 o2[32];
    #pragma unroll
    for (int i = 0; i < 32; i++) o2[i] = 0ull;
    float m = -CUDART_INF_F;
    float l = 0.f;

    for (int tile = 0; tile < SPLIT / KTILE; tile++) {
        const int j0 = ks * SPLIT + tile * KTILE;   /* key offset within batch */
        __syncthreads();
        {
            const float4* kp = (const float4*)(g_k + (size_t)(b * TT + j0) * HS);
            const float4* vp = (const float4*)(g_v + (size_t)(b * TT + j0) * HS);
            Ks[tid] = kp[tid]; Ks[tid + 128] = kp[tid + 128];
            Vs[tid] = vp[tid]; Vs[tid + 128] = vp[tid + 128];
        }
        __syncthreads();

        const int jr = r - j0;
        float sc[KTILE];
        float tmax = -CUDART_INF_F;
        #pragma unroll
        for (int j = 0; j < KTILE; j++) {
            const ulonglong2* kk = (const ulonglong2*)&Ks[j * 16];
            u64 a0 = 0ull, a1 = 0ull, a2 = 0ull, a3 = 0ull;
            #pragma unroll
            for (int d = 0; d < 16; d += 2) {
                ulonglong2 kv0 = kk[d];
                fma2(a0, q2[2 * d + 0], kv0.x);
                fma2(a1, q2[2 * d + 1], kv0.y);
                ulonglong2 kv1 = kk[d + 1];
                fma2(a2, q2[2 * d + 2], kv1.x);
                fma2(a3, q2[2 * d + 3], kv1.y);
            }
            add2(a0, a0, a2);
            add2(a1, a1, a3);
            float2 u = unpk(a0);
            float2 w = unpk(a1);
            float s = ((u.x + u.y) + (w.x + w.y)) * 8.0f;   /* * sqrt(hs) per ref */
            sc[j] = (j <= jr) ? s : -CUDART_INF_F;
            tmax = fmaxf(tmax, sc[j]);
        }

        float mnew = fmaxf(m, tmax);               /* finite after tile 0 */
        float scale = __expf(m - mnew);            /* m=-inf -> 0, safe   */
        m = mnew;
        l *= scale;
        u64 sd = dup2(scale);
        #pragma unroll
        for (int i = 0; i < 32; i++) mul2(o2[i], o2[i], sd);

        #pragma unroll
        for (int j = 0; j < KTILE; j++) {
            float p = __expf(sc[j] - mnew);
            l += p;
            u64 pd = dup2(p);
            const ulonglong2* vv = (const ulonglong2*)&Vs[j * 16];
            #pragma unroll
            for (int d = 0; d < 16; d++) {
                ulonglong2 w = vv[d];
                fma2(o2[2 * d + 0], pd, w.x);
                fma2(o2[2 * d + 1], pd, w.y);
            }
        }
    }

    g_pm[ks * ROWS + grow] = m;
    g_pl[ks * ROWS + grow] = l;
    ulonglong2* po = (ulonglong2*)(g_po + ((size_t)ks * ROWS + grow) * HS);
    #pragma unroll
    for (int i = 0; i < 16; i++) {
        ulonglong2 v; v.x = o2[2 * i]; v.y = o2[2 * i + 1];
        po[i] = v;
    }
}

/* ---------------- combine split partials -------------------------------- */
__global__ __launch_bounds__(256)
void attn_combine_kernel(float* __restrict__ out) {
    int t = blockIdx.x * blockDim.x + threadIdx.x;   /* (row, d4) */
    if (t >= ROWS * 16) return;
    int row = t >> 4;
    int d4  = t & 15;
    int smax = (row & (TT - 1)) >> 7;   /* active splits: 0..smax */

    float m = -CUDART_INF_F;
    for (int s = 0; s <= smax; s++) m = fmaxf(m, g_pm[s * ROWS + row]);

    float l = 0.f;
    float4 acc = make_float4(0.f, 0.f, 0.f, 0.f);
    for (int s = 0; s <= smax; s++) {
        float w = __expf(g_pm[s * ROWS + row] - m);
        l += g_pl[s * ROWS + row] * w;
        float4 p = ((const float4*)g_po)[((size_t)s * ROWS + row) * 16 + d4];
        acc.x = fmaf(w, p.x, acc.x);
        acc.y = fmaf(w, p.y, acc.y);
        acc.z = fmaf(w, p.z, acc.z);
        acc.w = fmaf(w, p.w, acc.w);
    }
    float inv = 1.f / l;
    ((float4*)out)[(size_t)row * 16 + d4] =
        make_float4(acc.x * inv, acc.y * inv, acc.z * inv, acc.w * inv);
}

/* ---------------- launch ------------------------------------------------ */
extern "C" void kernel_launch(void* const* d_in, const int* in_sizes, int n_in,
                              void* d_out, int out_size) {
    (void)in_sizes; (void)n_in; (void)out_size;
    const float* x  = (const float*)d_in[0];
    const float* Wq = (const float*)d_in[1];
    const float* bq = (const float*)d_in[2];
    const float* Wk = (const float*)d_in[3];
    const float* bk = (const float*)d_in[4];
    const float* Wv = (const float*)d_in[5];

    qkv_kernel<<<dim3(ROWS / 64, 3), 128>>>(x, Wq, bq, Wk, bk, Wv);
    attn_split_kernel<<<dim3(TRI, BB), 128>>>();
    attn_combine_kernel<<<(ROWS * 16 + 255) / 256, 256>>>((float*)d_out);
}